// round 2
// baseline (speedup 1.0000x reference)
#include <cuda_runtime.h>
#include <cstdint>

// CanineEmbeddings: multi-hash bucket embedding + concat + LayerNorm.
//   input_ids: [8, 8192] int (int64 per reference, but may arrive as int32 if
//              the reference ran without jax x64 — detected at runtime)
//   tables:    [8, 16384, 96] f32
//   ln_scale:  [768] f32
//   ln_bias:   [768] f32
//   out:       [8, 8192, 768] f32
//
// hidden index = h*96 + s   (shard h from hash table h)
// bucket_h = ((id + 1) * prime_h) % 16384  == low 14 bits of 32-bit product.

#define NUM_HASHES   8
#define NUM_BUCKETS  16384
#define SHARD        96
#define HIDDEN       768
#define TOKENS       (8 * 8192)
#define LN_EPS       1e-6f

__constant__ uint32_t c_primes[NUM_HASHES] = {31u, 43u, 59u, 61u, 73u, 97u, 103u, 113u};

// 1 => ids buffer is int64 elements, 0 => int32 elements.
__device__ int g_ids_is64;

__global__ void detect_id_width_kernel(const unsigned long long* __restrict__ ids64) {
    // If the buffer is really int32, reading as u64 combines pairs:
    //   v = lo + hi * 2^32 with hi an id in [0, 1114112) -> v > 0xFFFFFFFF
    // except when hi happens to be 0. Checking 8 consecutive u64 words makes a
    // false "int64" verdict require 8 independent zero ids: effectively never.
    bool is64 = true;
    #pragma unroll
    for (int i = 0; i < 8; i++) {
        if (ids64[i] > 0xFFFFFFFFull) is64 = false;
    }
    g_ids_is64 = is64 ? 1 : 0;
}

__global__ __launch_bounds__(192)
void canine_emb_ln_kernel(const void* __restrict__ ids_raw,
                          const float* __restrict__ tables,
                          const float* __restrict__ ln_scale,
                          const float* __restrict__ ln_bias,
                          float* __restrict__ out) {
    __shared__ float2 s_part[6];   // per-warp (sum, sumsq)
    __shared__ float2 s_stat;      // (mean, rstd)

    const int token = blockIdx.x;
    const int tid   = threadIdx.x;          // 0..191
    const int warp  = tid >> 5;             // 0..5
    const int lane  = tid & 31;

    // --- token id (broadcast load; all threads hit same L1 line) ---
    uint32_t id;
    if (g_ids_is64) {
        id = (uint32_t)((const unsigned long long*)ids_raw)[token];
    } else {
        id = ((const uint32_t*)ids_raw)[token];
    }

    // --- gather: thread t covers hidden floats [4t, 4t+4) ---
    // 24 threads per shard (24*4 = 96), so each float4 stays inside one row.
    const int h = tid / 24;                 // hash index 0..7
    const int c = tid - h * 24;             // float4 index within the 96-float row

    const uint32_t bucket = ((id + 1u) * c_primes[h]) & (NUM_BUCKETS - 1u);
    const float4* row = (const float4*)(tables + ((size_t)h * NUM_BUCKETS + bucket) * SHARD);
    const float4 v = __ldg(row + c);        // 384B contiguous per 24-thread group

    // --- block reduction for mean / var ---
    float s  = v.x + v.y + v.z + v.w;
    float sq = v.x * v.x + v.y * v.y + v.z * v.z + v.w * v.w;
    #pragma unroll
    for (int o = 16; o > 0; o >>= 1) {
        s  += __shfl_xor_sync(0xFFFFFFFFu, s,  o);
        sq += __shfl_xor_sync(0xFFFFFFFFu, sq, o);
    }
    if (lane == 0) s_part[warp] = make_float2(s, sq);
    __syncthreads();

    if (warp == 0) {
        float2 p = (lane < 6) ? s_part[lane] : make_float2(0.f, 0.f);
        #pragma unroll
        for (int o = 4; o > 0; o >>= 1) {   // reduce 8 slots (lanes 0..7), 6..7 are zero
            p.x += __shfl_xor_sync(0xFFFFFFFFu, p.x, o);
            p.y += __shfl_xor_sync(0xFFFFFFFFu, p.y, o);
        }
        if (lane == 0) {
            const float inv_n = 1.0f / (float)HIDDEN;
            float mean = p.x * inv_n;
            float var  = p.y * inv_n - mean * mean;
            s_stat = make_float2(mean, rsqrtf(var + LN_EPS));
        }
    }
    __syncthreads();

    const float mean = s_stat.x;
    const float rstd = s_stat.y;

    // --- normalize + affine + coalesced float4 store ---
    const float4 sc = __ldg((const float4*)ln_scale + tid);
    const float4 bi = __ldg((const float4*)ln_bias  + tid);
    float4 o4;
    o4.x = (v.x - mean) * rstd * sc.x + bi.x;
    o4.y = (v.y - mean) * rstd * sc.y + bi.y;
    o4.z = (v.z - mean) * rstd * sc.z + bi.z;
    o4.w = (v.w - mean) * rstd * sc.w + bi.w;

    ((float4*)out)[(size_t)token * (HIDDEN / 4) + tid] = o4;
}

extern "C" void kernel_launch(void* const* d_in, const int* in_sizes, int n_in,
                              void* d_out, int out_size) {
    const void*  ids     = d_in[0];                       // [8, 8192] int32 or int64
    const float* tables  = (const float*)d_in[1];         // [8, 16384, 96]
    const float* ln_s    = (const float*)d_in[2];         // [768]
    const float* ln_b    = (const float*)d_in[3];         // [768]
    float*       out     = (float*)d_out;                 // [8, 8192, 768]

    detect_id_width_kernel<<<1, 1>>>((const unsigned long long*)ids);
    canine_emb_ln_kernel<<<TOKENS, 192>>>(ids, tables, ln_s, ln_b, out);
}

// round 5
// speedup vs baseline: 1.7602x; 1.7602x over previous
#include <cuda_runtime.h>
#include <cstdint>

// CanineEmbeddings: multi-hash bucket embedding + concat + LayerNorm.
//   input_ids: [8, 8192] int (int64 per reference; int32 if jax x64 was off —
//              detected inline from the raw buffer)
//   tables:    [8, 16384, 96] f32   (50.3 MB — L2 resident)
//   ln_scale:  [768] f32
//   ln_bias:   [768] f32
//   out:       [8, 8192, 768] f32   (201 MB, streamed with .cs)
//
// hidden index = h*96 + c*4..c*4+3 ; bucket_h = ((id+1)*prime_h) & 16383.
//
// Design: one WARP per token, barrier-free.
//   lane l owns float4 indices j = k*32 + l, k = 0..5  (6*32 = 192 = 768/4)
//   -> 6 independent LDG.128 gathers in flight per thread (MLP=6)
//   -> mean/var via pure warp shuffle (no __syncthreads, no smem)
//   -> stores: 32 consecutive float4 per k, fully coalesced, __stcs.

#define NUM_HASHES   8
#define NUM_BUCKETS  16384
#define SHARD        96
#define HIDDEN       768
#define TOKENS       (8 * 8192)
#define WARPS_PER_BLOCK 8
#define LN_EPS       1e-6f

__constant__ uint32_t c_primes[NUM_HASHES] = {31u, 43u, 59u, 61u, 73u, 97u, 103u, 113u};

__global__ __launch_bounds__(32 * WARPS_PER_BLOCK)
void canine_emb_ln_kernel(const void* __restrict__ ids_raw,
                          const float* __restrict__ tables,
                          const float* __restrict__ ln_scale,
                          const float* __restrict__ ln_bias,
                          float* __restrict__ out) {
    const int lane  = threadIdx.x & 31;
    const int warp  = threadIdx.x >> 5;
    const int token = blockIdx.x * WARPS_PER_BLOCK + warp;

    // --- inline id-width detection (uniform across all threads) ---
    // int32 layout read as u64 pairs gives hi-word = a nonzero id (w.p.
    // ~1 - 1e-6 each); 8 consecutive u64 > 0xFFFFFFFF checks make a false
    // "int64" verdict require 8 independent zero ids: effectively never.
    // These 8 loads hit the same L1 lines for every warp after wave 1.
    const unsigned long long* ids64 = (const unsigned long long*)ids_raw;
    bool is64 = true;
    #pragma unroll
    for (int i = 0; i < 8; i++) {
        if (ids64[i] > 0xFFFFFFFFull) is64 = false;
    }

    // --- token id (broadcast load: all 32 lanes, one address) ---
    uint32_t id;
    if (is64) {
        id = (uint32_t)ids64[token];
    } else {
        id = ((const uint32_t*)ids_raw)[token];
    }
    const uint32_t idp1 = id + 1u;

    // --- 6 independent gathers ---
    float4 v[6];
    #pragma unroll
    for (int k = 0; k < 6; k++) {
        const int j = k * 32 + lane;        // float4 index in [0,192)
        const int h = j / 24;               // hash/shard index 0..7
        const int c = j - h * 24;           // float4 offset within 96-float row
        const uint32_t bucket = (idp1 * c_primes[h]) & (NUM_BUCKETS - 1u);
        const float4* row =
            (const float4*)(tables + ((size_t)h * NUM_BUCKETS + bucket) * SHARD);
        v[k] = __ldg(row + c);
    }

    // --- mean / var: per-thread partial then 5-step warp shuffle ---
    float s = 0.f, sq = 0.f;
    #pragma unroll
    for (int k = 0; k < 6; k++) {
        s  += v[k].x + v[k].y + v[k].z + v[k].w;
        sq += v[k].x * v[k].x + v[k].y * v[k].y
            + v[k].z * v[k].z + v[k].w * v[k].w;
    }
    #pragma unroll
    for (int o = 16; o > 0; o >>= 1) {
        s  += __shfl_xor_sync(0xFFFFFFFFu, s,  o);
        sq += __shfl_xor_sync(0xFFFFFFFFu, sq, o);
    }
    const float inv_n = 1.0f / (float)HIDDEN;
    const float mean  = s * inv_n;
    const float rstd  = rsqrtf(sq * inv_n - mean * mean + LN_EPS);

    // --- normalize + affine, streaming coalesced stores ---
    float4* out4 = (float4*)out + (size_t)token * (HIDDEN / 4);
    #pragma unroll
    for (int k = 0; k < 6; k++) {
        const int j = k * 32 + lane;
        const float4 sc = __ldg((const float4*)ln_scale + j);
        const float4 bi = __ldg((const float4*)ln_bias  + j);
        float4 o4;
        o4.x = (v[k].x - mean) * rstd * sc.x + bi.x;
        o4.y = (v[k].y - mean) * rstd * sc.y + bi.y;
        o4.z = (v[k].z - mean) * rstd * sc.z + bi.z;
        o4.w = (v[k].w - mean) * rstd * sc.w + bi.w;
        __stcs(out4 + j, o4);               // streaming: keep tables in L2
    }
}

extern "C" void kernel_launch(void* const* d_in, const int* in_sizes, int n_in,
                              void* d_out, int out_size) {
    const void*  ids    = d_in[0];                 // [8, 8192] int32 or int64
    const float* tables = (const float*)d_in[1];   // [8, 16384, 96]
    const float* ln_s   = (const float*)d_in[2];   // [768]
    const float* ln_b   = (const float*)d_in[3];   // [768]
    float*       out    = (float*)d_out;           // [8, 8192, 768]

    canine_emb_ln_kernel<<<TOKENS / WARPS_PER_BLOCK, 32 * WARPS_PER_BLOCK>>>(
        ids, tables, ln_s, ln_b, out);
}